// round 9
// baseline (speedup 1.0000x reference)
#include <cuda_runtime.h>
#include <cuda_bf16.h>

// EMA: y[n] = w*x[n] + (1-w)*y[n-1], scan over last (contiguous) axis.
// Shapes: input (16,8,256,2048) f32, initial_state (16,8,256), weight (8,256).
// One warp per series (32768 series).
// R9: 8 elements per lane (two adjacent float4 = 32 contiguous bytes/lane),
// warp chunk = 256 frames, 8 chunks. Kogge-Stone scan still 5 steps with
// constants omw^(8*2^k) -> shuffle cost per byte halves vs R8, and carry-chain
// crossings drop 16 -> 8. Depth-2 pipeline, streaming ld/st.

#define N_FRAMES 2048
#define SERIES_PER_WB 2048   /* N_RES * N_BINS = 8*256 */
#define N_SERIES 32768       /* 16*8*256 */

__global__ __launch_bounds__(256)
void ema_scan_kernel(const float* __restrict__ x,
                     const float* __restrict__ init_state,
                     const float* __restrict__ weight,
                     float* __restrict__ y) {
    const int warp_global = (blockIdx.x * blockDim.x + threadIdx.x) >> 5;
    const int lane = threadIdx.x & 31;
    if (warp_global >= N_SERIES) return;

    const int series = warp_global;

    // weight index = series % (N_RES*N_BINS); clamp to [0,1]
    const float w_raw = weight[series & (SERIES_PER_WB - 1)];
    const float w   = fminf(fmaxf(w_raw, 0.0f), 1.0f);
    const float omw = 1.0f - w;

    // Powers of the 8-element decay: Q[k] = omw^(8*2^k)
    const float omw2 = omw * omw;
    const float omw4 = omw2 * omw2;
    const float Q1  = omw4 * omw4;   // omw^8
    const float Q2  = Q1 * Q1;       // omw^16
    const float Q4  = Q2 * Q2;       // omw^32
    const float Q8  = Q4 * Q4;       // omw^64
    const float Q16 = Q8 * Q8;       // omw^128

    // Apow = omw^(8*lane): carry multiplier for this lane's exclusive state.
    float Apow = 1.0f;
    if (lane & 1)  Apow *= Q1;
    if (lane & 2)  Apow *= Q2;
    if (lane & 4)  Apow *= Q4;
    if (lane & 8)  Apow *= Q8;
    if (lane & 16) Apow *= Q16;

    float carry = init_state[series];

    // Each lane owns 32 contiguous bytes: frames [chunk*256 + lane*8, +8).
    const float4* __restrict__ xin  =
        reinterpret_cast<const float4*>(x + (size_t)series * N_FRAMES);
    float4* __restrict__ yout =
        reinterpret_cast<float4*>(y + (size_t)series * N_FRAMES);

    // Depth-2 pipeline: chunk it+1 loads while chunk it scans.
    float4 u = __ldcs(&xin[lane * 2]);
    float4 v = __ldcs(&xin[lane * 2 + 1]);

    #pragma unroll
    for (int it = 0; it < N_FRAMES / 256; ++it) {
        float4 nu, nv;
        if (it < N_FRAMES / 256 - 1) {
            nu = __ldcs(&xin[(it + 1) * 64 + lane * 2]);
            nv = __ldcs(&xin[(it + 1) * 64 + lane * 2 + 1]);
        }

        // Local composite: B = EMA of this lane's 8 x's starting from 0.
        float B = w * u.x;
        B = fmaf(omw, B, w * u.y);
        B = fmaf(omw, B, w * u.z);
        B = fmaf(omw, B, w * u.w);
        B = fmaf(omw, B, w * v.x);
        B = fmaf(omw, B, w * v.y);
        B = fmaf(omw, B, w * v.z);
        B = fmaf(omw, B, w * v.w);

        // B-only Kogge-Stone scan with constant segment multipliers.
        float Bu;
        Bu = __shfl_up_sync(0xFFFFFFFFu, B, 1);
        if (lane >= 1)  B = fmaf(Q1,  Bu, B);
        Bu = __shfl_up_sync(0xFFFFFFFFu, B, 2);
        if (lane >= 2)  B = fmaf(Q2,  Bu, B);
        Bu = __shfl_up_sync(0xFFFFFFFFu, B, 4);
        if (lane >= 4)  B = fmaf(Q4,  Bu, B);
        Bu = __shfl_up_sync(0xFFFFFFFFu, B, 8);
        if (lane >= 8)  B = fmaf(Q8,  Bu, B);
        Bu = __shfl_up_sync(0xFFFFFFFFu, B, 16);
        if (lane >= 16) B = fmaf(Q16, Bu, B);

        // Exclusive incoming state: y_in = omw^(8*lane)*carry + B[lane-1].
        float Be = __shfl_up_sync(0xFFFFFFFFu, B, 1);
        float y_in = fmaf(Apow, carry, (lane == 0) ? 0.0f : Be);

        // Reproduce the exact sequential per-element recurrence locally.
        float y0 = fmaf(omw, y_in, w * u.x);
        float y1 = fmaf(omw, y0,  w * u.y);
        float y2 = fmaf(omw, y1,  w * u.z);
        float y3 = fmaf(omw, y2,  w * u.w);
        float y4 = fmaf(omw, y3,  w * v.x);
        float y5 = fmaf(omw, y4,  w * v.y);
        float y6 = fmaf(omw, y5,  w * v.z);
        float y7 = fmaf(omw, y6,  w * v.w);

        __stcs(&yout[it * 64 + lane * 2],     make_float4(y0, y1, y2, y3));
        __stcs(&yout[it * 64 + lane * 2 + 1], make_float4(y4, y5, y6, y7));

        // Carry = lane 31's final value.
        carry = __shfl_sync(0xFFFFFFFFu, y7, 31);
        u = nu;
        v = nv;
    }
}

extern "C" void kernel_launch(void* const* d_in, const int* in_sizes, int n_in,
                              void* d_out, int out_size) {
    const float* x    = (const float*)d_in[0];   // input (16,8,256,2048)
    const float* init = (const float*)d_in[1];   // initial_state (16,8,256)
    const float* wgt  = (const float*)d_in[2];   // weight (8,256)
    float* y = (float*)d_out;

    // 32768 warps, 8 warps (256 threads) per block -> 4096 blocks.
    const int threads = 256;
    const int blocks = (N_SERIES * 32) / threads;
    ema_scan_kernel<<<blocks, threads>>>(x, init, wgt, y);
}

// round 11
// speedup vs baseline: 1.0229x; 1.0229x over previous
#include <cuda_runtime.h>
#include <cuda_bf16.h>

// EMA: y[n] = w*x[n] + (1-w)*y[n-1], scan over last (contiguous) axis.
// Shapes: input (16,8,256,2048) f32, initial_state (16,8,256), weight (8,256).
// One warp per series (32768 series), constant-decay B-only Kogge-Stone scan,
// ILP-2 chunk pairing (R8: two independent 5-deep shuffle chains per 256
// frames; carry enters only via the final affine correction).
// R10: chunk0's store issues before chunk1's dependent recurrence chain, and
// the next-iteration carry is computed before the stores, so stores drain
// while dependent math runs. Everything else is the proven R8 structure.

#define N_FRAMES 2048
#define SERIES_PER_WB 2048   /* N_RES * N_BINS = 8*256 */
#define N_SERIES 32768       /* 16*8*256 */

__global__ __launch_bounds__(256)
void ema_scan_kernel(const float* __restrict__ x,
                     const float* __restrict__ init_state,
                     const float* __restrict__ weight,
                     float* __restrict__ y) {
    const int warp_global = (blockIdx.x * blockDim.x + threadIdx.x) >> 5;
    const int lane = threadIdx.x & 31;
    if (warp_global >= N_SERIES) return;

    const int series = warp_global;

    // weight index = series % (N_RES*N_BINS); clamp to [0,1]
    const float w_raw = weight[series & (SERIES_PER_WB - 1)];
    const float w   = fminf(fmaxf(w_raw, 0.0f), 1.0f);
    const float omw = 1.0f - w;

    // Powers of the 4-element decay: P[k] = omw^(4*2^k)
    const float P1  = ((omw * omw) * (omw * omw));  // omw^4
    const float P2  = P1 * P1;                      // omw^8
    const float P4  = P2 * P2;                      // omw^16
    const float P8  = P4 * P4;                      // omw^32
    const float P16 = P8 * P8;                      // omw^64
    const float P32 = P16 * P16;                    // omw^128 (full-chunk decay)

    // Apow = omw^(4*lane): carry multiplier for this lane's exclusive state.
    float Apow = 1.0f;
    if (lane & 1)  Apow *= P1;
    if (lane & 2)  Apow *= P2;
    if (lane & 4)  Apow *= P4;
    if (lane & 8)  Apow *= P8;
    if (lane & 16) Apow *= P16;

    float carry = init_state[series];

    const float4* __restrict__ xin  =
        reinterpret_cast<const float4*>(x + (size_t)series * N_FRAMES);
    float4* __restrict__ yout =
        reinterpret_cast<float4*>(y + (size_t)series * N_FRAMES);

    // Depth-2 pipeline over chunk PAIRS: pair t+1 loads while pair t scans.
    float4 v0 = __ldcs(&xin[lane]);
    float4 v1 = __ldcs(&xin[32 + lane]);

    #pragma unroll
    for (int t = 0; t < N_FRAMES / 256; ++t) {
        float4 n0, n1;
        if (t < N_FRAMES / 256 - 1) {
            n0 = __ldcs(&xin[(2 * t + 2) * 32 + lane]);
            n1 = __ldcs(&xin[(2 * t + 3) * 32 + lane]);
        }

        // Local composites (independent).
        float B0 = w * v0.x;
        B0 = fmaf(omw, B0, w * v0.y);
        B0 = fmaf(omw, B0, w * v0.z);
        B0 = fmaf(omw, B0, w * v0.w);

        float B1 = w * v1.x;
        B1 = fmaf(omw, B1, w * v1.y);
        B1 = fmaf(omw, B1, w * v1.z);
        B1 = fmaf(omw, B1, w * v1.w);

        // Two independent Kogge-Stone B-scans, interleaved for ILP.
        float Bu0, Bu1;
        Bu0 = __shfl_up_sync(0xFFFFFFFFu, B0, 1);
        Bu1 = __shfl_up_sync(0xFFFFFFFFu, B1, 1);
        if (lane >= 1)  { B0 = fmaf(P1,  Bu0, B0); B1 = fmaf(P1,  Bu1, B1); }
        Bu0 = __shfl_up_sync(0xFFFFFFFFu, B0, 2);
        Bu1 = __shfl_up_sync(0xFFFFFFFFu, B1, 2);
        if (lane >= 2)  { B0 = fmaf(P2,  Bu0, B0); B1 = fmaf(P2,  Bu1, B1); }
        Bu0 = __shfl_up_sync(0xFFFFFFFFu, B0, 4);
        Bu1 = __shfl_up_sync(0xFFFFFFFFu, B1, 4);
        if (lane >= 4)  { B0 = fmaf(P4,  Bu0, B0); B1 = fmaf(P4,  Bu1, B1); }
        Bu0 = __shfl_up_sync(0xFFFFFFFFu, B0, 8);
        Bu1 = __shfl_up_sync(0xFFFFFFFFu, B1, 8);
        if (lane >= 8)  { B0 = fmaf(P8,  Bu0, B0); B1 = fmaf(P8,  Bu1, B1); }
        Bu0 = __shfl_up_sync(0xFFFFFFFFu, B0, 16);
        Bu1 = __shfl_up_sync(0xFFFFFFFFu, B1, 16);
        if (lane >= 16) { B0 = fmaf(P16, Bu0, B0); B1 = fmaf(P16, Bu1, B1); }

        // Exclusive prefixes and chunk totals.
        float B0e = __shfl_up_sync(0xFFFFFFFFu, B0, 1);
        float B1e = __shfl_up_sync(0xFFFFFFFFu, B1, 1);
        float T0  = __shfl_sync(0xFFFFFFFFu, B0, 31);
        float T1  = __shfl_sync(0xFFFFFFFFu, B1, 31);

        // Incoming states; next-iteration carry resolved BEFORE any stores so
        // the following iteration's scan front is not store-ordered.
        float y_in0  = fmaf(Apow, carry, (lane == 0) ? 0.0f : B0e);
        float state1 = fmaf(P32, carry, T0);            // state after chunk0
        float y_in1  = fmaf(Apow, state1, (lane == 0) ? 0.0f : B1e);
        carry        = fmaf(P32, state1, T1);           // state after chunk1

        // Chunk0 recurrence + immediate store (drains while chunk1 computes).
        float a0 = fmaf(omw, y_in0, w * v0.x);
        float a1 = fmaf(omw, a0,    w * v0.y);
        float a2 = fmaf(omw, a1,    w * v0.z);
        float a3 = fmaf(omw, a2,    w * v0.w);
        __stcs(&yout[(2 * t) * 32 + lane], make_float4(a0, a1, a2, a3));

        // Chunk1 recurrence + store.
        float c0 = fmaf(omw, y_in1, w * v1.x);
        float c1 = fmaf(omw, c0,    w * v1.y);
        float c2 = fmaf(omw, c1,    w * v1.z);
        float c3 = fmaf(omw, c2,    w * v1.w);
        __stcs(&yout[(2 * t + 1) * 32 + lane], make_float4(c0, c1, c2, c3));

        v0 = n0;
        v1 = n1;
    }
}

extern "C" void kernel_launch(void* const* d_in, const int* in_sizes, int n_in,
                              void* d_out, int out_size) {
    const float* x    = (const float*)d_in[0];   // input (16,8,256,2048)
    const float* init = (const float*)d_in[1];   // initial_state (16,8,256)
    const float* wgt  = (const float*)d_in[2];   // weight (8,256)
    float* y = (float*)d_out;

    // 32768 warps, 8 warps (256 threads) per block -> 4096 blocks
    // (empirically best launch shape: fine blocks, HW-balanced waves).
    const int threads = 256;
    const int blocks = (N_SERIES * 32) / threads;
    ema_scan_kernel<<<blocks, threads>>>(x, init, wgt, y);
}